// round 4
// baseline (speedup 1.0000x reference)
#include <cuda_runtime.h>
#include <math.h>

// Problem dims
#define Dv   7686
#define Mv   2048
#define Hv   512
#define Ov   8
#define Nv   8206          // D + H + O
#define OUTC 520           // H + O (columns needed from sweep 1)

// ---------------- scratch (__device__ globals; no allocation allowed) ----------------
static __device__ float g_q [(size_t)Mv * Dv];     // 63 MB
static __device__ float g_k [(size_t)Mv * Dv];     // 63 MB
static __device__ float g_sc[(size_t)Mv * Mv];     // 16.8 MB
static __device__ float g_rowmax[Mv];
static __device__ float g_rowinv[Mv];
static __device__ float g_spart[16 * Mv];
static __device__ float g_s[Mv];
static __device__ float g_upart[16 * Dv];
static __device__ float g_u[Dv];
static __device__ float g_cpart[32 * Dv];
static __device__ float g_vals[Nv];                // [0:D)=context, [D:N)=tanh layer-1
static __device__ float g_zpart[64 * OUTC];
static __device__ float g_opart[33 * Ov];

// ---------------- 128x128x16 fp32 SGEMM, 8x8 register tile, 256 threads ----------------
// TRANSB=false: C[M,Nc] = A[M,K] * B[K,Nc] (+bias, *scale)
// TRANSB=true : C[M,Nc] = A[M,K] * B[Nc,K]^T (+bias, *scale)
template <bool TRANSB>
__global__ void __launch_bounds__(256, 2)
k_sgemm(const float* __restrict__ A, const float* __restrict__ B,
        const float* __restrict__ bias, float* __restrict__ C,
        int Mr, int Nc, int Kc, int lda, int ldb, int ldc, float scale)
{
    __shared__ float As[16][136];   // [k][m], padded: keeps float4 alignment, reduces STS conflicts
    __shared__ float Bs[16][136];   // [k][n]

    const int tid  = threadIdx.x;
    const int tx   = tid & 15;          // 0..15 -> N micro-tile
    const int ty   = tid >> 4;          // 0..15 -> M micro-tile
    const int row0 = blockIdx.y * 128;
    const int col0 = blockIdx.x * 128;

    // load mappings
    const int aR = tid >> 4;            // 0..15, +16*it covers 128 rows
    const int aK = tid & 15;            // k within tile
    const int bK = tid >> 7;            // 0..1, +2*it covers 16 k
    const int bN = tid & 127;           // n within tile (coalesced)

    float acc[8][8];
#pragma unroll
    for (int i = 0; i < 8; ++i)
#pragma unroll
        for (int j = 0; j < 8; ++j) acc[i][j] = 0.f;

    for (int k0 = 0; k0 < Kc; k0 += 16) {
        // stage A tile: As[k][m]
#pragma unroll
        for (int it = 0; it < 8; ++it) {
            int r  = aR + 16 * it;
            int gr = row0 + r;
            int gk = k0 + aK;
            float v = 0.f;
            if (gr < Mr && gk < Kc) v = A[(size_t)gr * lda + gk];
            As[aK][r] = v;
        }
        // stage B tile: Bs[k][n]
        if (TRANSB) {
#pragma unroll
            for (int it = 0; it < 8; ++it) {
                int n  = aR + 16 * it;
                int gn = col0 + n;
                int gk = k0 + aK;
                float v = 0.f;
                if (gn < Nc && gk < Kc) v = B[(size_t)gn * ldb + gk];
                Bs[aK][n] = v;
            }
        } else {
#pragma unroll
            for (int it = 0; it < 8; ++it) {
                int kk = bK + 2 * it;
                int gk = k0 + kk;
                int gn = col0 + bN;
                float v = 0.f;
                if (gk < Kc && gn < Nc) v = B[(size_t)gk * ldb + gn];
                Bs[kk][bN] = v;
            }
        }
        __syncthreads();

#pragma unroll
        for (int kk = 0; kk < 16; ++kk) {
            float4 a0 = *reinterpret_cast<const float4*>(&As[kk][ty * 8]);
            float4 a1 = *reinterpret_cast<const float4*>(&As[kk][ty * 8 + 4]);
            float4 b0 = *reinterpret_cast<const float4*>(&Bs[kk][tx * 8]);
            float4 b1 = *reinterpret_cast<const float4*>(&Bs[kk][tx * 8 + 4]);
            float ra[8] = {a0.x, a0.y, a0.z, a0.w, a1.x, a1.y, a1.z, a1.w};
            float rb[8] = {b0.x, b0.y, b0.z, b0.w, b1.x, b1.y, b1.z, b1.w};
#pragma unroll
            for (int i = 0; i < 8; ++i)
#pragma unroll
                for (int j = 0; j < 8; ++j)
                    acc[i][j] = fmaf(ra[i], rb[j], acc[i][j]);
        }
        __syncthreads();
    }

    const bool hasB = (bias != nullptr);
#pragma unroll
    for (int i = 0; i < 8; ++i) {
        int gr = row0 + ty * 8 + i;
        if (gr >= Mr) continue;
#pragma unroll
        for (int j = 0; j < 8; ++j) {
            int gc = col0 + tx * 8 + j;
            if (gc < Nc) {
                float v = acc[i][j] * scale;
                if (hasB) v += bias[gc];
                C[(size_t)gr * ldc + gc] = v;
            }
        }
    }
}

// ---------------- softmax row stats: max and 1/sumexp per row ----------------
__global__ void k_rowstat()
{
    const int row = blockIdx.x;
    const float* p = g_sc + (size_t)row * Mv;
    __shared__ float red[256];
    const int t = threadIdx.x;

    float m = -3.4e38f;
    for (int j = t; j < Mv; j += 256) m = fmaxf(m, p[j]);
    red[t] = m; __syncthreads();
    for (int s = 128; s > 0; s >>= 1) {
        if (t < s) red[t] = fmaxf(red[t], red[t + s]);
        __syncthreads();
    }
    m = red[0];
    __syncthreads();

    float sum = 0.f;
    for (int j = t; j < Mv; j += 256) sum += expf(p[j] - m);
    red[t] = sum; __syncthreads();
    for (int s = 128; s > 0; s >>= 1) {
        if (t < s) red[t] += red[t + s];
        __syncthreads();
    }
    if (t == 0) { g_rowmax[row] = m; g_rowinv[row] = 1.f / red[0]; }
}

// column partial sums of the softmax matrix. grid: (Mv/256, 16); 128 rows/chunk.
__global__ void k_colsum_part()
{
    const int j = blockIdx.x * 256 + threadIdx.x;
    const int c = blockIdx.y;
    float acc = 0.f;
    const int i0 = c * (Mv / 16), i1 = i0 + (Mv / 16);
    for (int i = i0; i < i1; ++i)
        acc += expf(g_sc[(size_t)i * Mv + j] - g_rowmax[i]) * g_rowinv[i];
    g_spart[c * Mv + j] = acc;
}

__global__ void k_s_reduce()
{
    const int j = blockIdx.x * 256 + threadIdx.x;
    float acc = 0.f;
    for (int c = 0; c < 16; ++c) acc += g_spart[c * Mv + j];
    g_s[j] = acc * (1.f / (float)Mv);
}

// u = s^T X.  grid: (ceil(D/256), 16); 128 rows/chunk.
__global__ void k_u_part(const float* __restrict__ X)
{
    const int j = blockIdx.x * 256 + threadIdx.x;
    if (j >= Dv) return;
    const int c = blockIdx.y;
    const int i0 = c * (Mv / 16), i1 = i0 + (Mv / 16);
    float acc = 0.f;
    for (int i = i0; i < i1; ++i)
        acc = fmaf(g_s[i], X[(size_t)i * Dv + j], acc);
    g_upart[c * Dv + j] = acc;
}

__global__ void k_u_reduce()
{
    const int j = blockIdx.x * 256 + threadIdx.x;
    if (j >= Dv) return;
    float acc = 0.f;
    for (int c = 0; c < 16; ++c) acc += g_upart[c * Dv + j];
    g_u[j] = acc;
}

// context = u @ Wv + bv  ->  g_vals[0:D].  grid: (ceil(D/256), 32).
__global__ void k_ctx_part(const float* __restrict__ Wv)
{
    const int j = blockIdx.x * 256 + threadIdx.x;
    if (j >= Dv) return;
    const int c = blockIdx.y;
    const int CR = (Dv + 31) / 32;         // 241
    const int i0 = c * CR;
    const int i1 = min(i0 + CR, Dv);
    float acc = 0.f;
    for (int i = i0; i < i1; ++i)
        acc = fmaf(g_u[i], Wv[(size_t)i * Dv + j], acc);
    g_cpart[c * Dv + j] = acc;
}

__global__ void k_ctx_reduce(const float* __restrict__ bv)
{
    const int j = blockIdx.x * 256 + threadIdx.x;
    if (j >= Dv) return;
    float acc = 0.f;
    for (int c = 0; c < 32; ++c) acc += g_cpart[c * Dv + j];
    g_vals[j] = acc + bv[j];               // vals[:D] = context
}

// sweep 1: z[j] = sum_{i<D} context[i] * (mu+sg*eps)[i][j], only cols j in [D, N).
// grid: (ceil(520/256), 64); ~121 rows/chunk.
__global__ void k_sweep1_part(const float* __restrict__ wmu,
                              const float* __restrict__ wsg,
                              const float* __restrict__ ew)
{
    const int jl = blockIdx.x * 256 + threadIdx.x;
    if (jl >= OUTC) return;
    const int j = Dv + jl;
    const int c = blockIdx.y;
    const int SR = (Dv + 63) / 64;         // 121
    const int i0 = c * SR;
    const int i1 = min(i0 + SR, Dv);
    float acc = 0.f;
    for (int i = i0; i < i1; ++i) {
        size_t idx = (size_t)i * Nv + j;
        acc = fmaf(g_vals[i], fmaf(wsg[idx], ew[idx], wmu[idx]), acc);
    }
    g_zpart[c * OUTC + jl] = acc;
}

__global__ void k_sweep1_reduce(const float* __restrict__ bmu,
                                const float* __restrict__ bsg,
                                const float* __restrict__ eb)
{
    const int jl = blockIdx.x * 256 + threadIdx.x;
    if (jl >= OUTC) return;
    const int j = Dv + jl;
    float z = 0.f;
    for (int c = 0; c < 64; ++c) z += g_zpart[c * OUTC + jl];
    float b = fmaf(bsg[j], eb[j], bmu[j]);
    g_vals[j] = tanhf(z + b);
}

// sweep 2: only the 8 output columns. grid: 33 blocks x 256 threads (row-parallel).
__global__ void k_sweep2_part(const float* __restrict__ wmu,
                              const float* __restrict__ wsg,
                              const float* __restrict__ ew)
{
    const int i = blockIdx.x * 256 + threadIdx.x;
    float a[Ov];
#pragma unroll
    for (int o = 0; o < Ov; ++o) a[o] = 0.f;
    if (i < Nv) {
        const float vi = g_vals[i];
        const size_t base = (size_t)i * Nv + (Dv + Hv);
#pragma unroll
        for (int o = 0; o < Ov; ++o)
            a[o] = vi * fmaf(wsg[base + o], ew[base + o], wmu[base + o]);
    }
    __shared__ float red[256];
    const int t = threadIdx.x;
#pragma unroll
    for (int o = 0; o < Ov; ++o) {
        red[t] = a[o];
        __syncthreads();
        for (int s = 128; s > 0; s >>= 1) {
            if (t < s) red[t] += red[t + s];
            __syncthreads();
        }
        if (t == 0) g_opart[blockIdx.x * Ov + o] = red[0];
        __syncthreads();
    }
}

__global__ void k_final(float* __restrict__ out,
                        const float* __restrict__ bmu,
                        const float* __restrict__ bsg,
                        const float* __restrict__ eb)
{
    const int t = threadIdx.x;
    if (t < Ov) {
        float z = 0.f;
        for (int c = 0; c < 33; ++c) z += g_opart[c * Ov + t];
        const int j = Dv + Hv + t;
        float b = fmaf(bsg[j], eb[j], bmu[j]);
        float h = tanhf(z + b);
        out[t] = 1.f / (1.f + expf(-h));
    }
}

// ---------------- launch ----------------
extern "C" void kernel_launch(void* const* d_in, const int* in_sizes, int n_in,
                              void* d_out, int out_size)
{
    const float* X   = (const float*)d_in[0];   // [M, D]
    const float* Wq  = (const float*)d_in[1];   // [D, D]
    const float* bq  = (const float*)d_in[2];   // [D]
    const float* Wk  = (const float*)d_in[3];
    const float* bk  = (const float*)d_in[4];
    const float* Wv  = (const float*)d_in[5];
    const float* bv  = (const float*)d_in[6];
    const float* wmu = (const float*)d_in[7];   // [N, N]
    const float* wsg = (const float*)d_in[8];
    const float* bmu = (const float*)d_in[9];   // [N]
    const float* bsg = (const float*)d_in[10];
    const float* ew  = (const float*)d_in[11];  // [N, N]
    const float* eb  = (const float*)d_in[12];  // [N]
    float* out = (float*)d_out;

    float *pq = nullptr, *pk = nullptr, *psc = nullptr;
    cudaGetSymbolAddress((void**)&pq,  g_q);
    cudaGetSymbolAddress((void**)&pk,  g_k);
    cudaGetSymbolAddress((void**)&psc, g_sc);

    const float scScale = (float)(1.0 / sqrt((double)Dv));

    dim3 gBig((Dv + 127) / 128, Mv / 128);     // 61 x 16
    k_sgemm<false><<<gBig, 256>>>(X, Wq, bq, pq, Mv, Dv, Dv, Dv, Dv, Dv, 1.f);
    k_sgemm<false><<<gBig, 256>>>(X, Wk, bk, pk, Mv, Dv, Dv, Dv, Dv, Dv, 1.f);

    dim3 gSc(Mv / 128, Mv / 128);              // 16 x 16
    k_sgemm<true><<<gSc, 256>>>(pq, pk, nullptr, psc, Mv, Mv, Dv, Dv, Dv, Mv, scScale);

    k_rowstat<<<Mv, 256>>>();
    k_colsum_part<<<dim3(Mv / 256, 16), 256>>>();
    k_s_reduce<<<Mv / 256, 256>>>();

    k_u_part<<<dim3((Dv + 255) / 256, 16), 256>>>(X);
    k_u_reduce<<<(Dv + 255) / 256, 256>>>();

    k_ctx_part<<<dim3((Dv + 255) / 256, 32), 256>>>(Wv);
    k_ctx_reduce<<<(Dv + 255) / 256, 256>>>(bv);

    k_sweep1_part<<<dim3((OUTC + 255) / 256, 64), 256>>>(wmu, wsg, ew);
    k_sweep1_reduce<<<(OUTC + 255) / 256, 256>>>(bmu, bsg, eb);

    k_sweep2_part<<<(Nv + 255) / 256, 256>>>(wmu, wsg, ew);
    k_final<<<1, 32>>>(out, bmu, bsg, eb);
}

// round 8
// speedup vs baseline: 1.5157x; 1.5157x over previous
#include <cuda_runtime.h>
#include <math.h>
#include <stdint.h>
#include <mma.h>

using namespace nvcuda;

// Problem dims
#define Dv   7686
#define Mv   2048
#define Hv   512
#define Ov   8
#define Nv   8206          // D + H + O
#define OUTC 520           // H + O

// ---------------- scratch (__device__ globals) ----------------
static __device__ float g_q [(size_t)Mv * Dv];
static __device__ float g_k [(size_t)Mv * Dv];
static __device__ float g_sc[(size_t)Mv * Mv];
static __device__ float g_rowmax[Mv];
static __device__ float g_rowinv[Mv];
static __device__ float g_spart[16 * Mv];
static __device__ float g_s[Mv];
static __device__ float g_upart[16 * Dv];
static __device__ float g_u[Dv];
static __device__ float g_cpart[32 * Dv];
static __device__ float g_vals[Nv];
static __device__ float g_zpart[64 * OUTC];
static __device__ float g_opart[33 * Ov];

__device__ __forceinline__ float to_tf32(float x) {
    float r;
    asm("cvt.rna.tf32.f32 %0, %1;" : "=f"(r) : "f"(x));
    return r;
}

// ---------------- SMEM tile layout (floats) ----------------
// As[b]: 128 x 40 (k-chunk 32 + pad 8), 5120 floats each
// Bs[b]: 5120 floats each (row-major 32x136 or col-major 128x40)
// epilogue staging reuses [0 .. 128*132) floats
#define AS_OFF(b)  ((b) * 5120)
#define BS_OFF(b)  (10240 + (b) * 5120)
#define GEMM_SMEM  (20480 * 4)   /* 81920 bytes */

// ---------------- tile loaders (fp32 -> tf32 via cvt.rna at SMEM store) ----------------
// NOTE: global row strides (7686 floats = 30744 B) are only 8-byte aligned for odd
// rows, so wide loads must be float2 (LDG.64), never float4.

// A tile: rows [row0,row0+128) always valid, k chunk of 32 may clip at Kc.
__device__ __forceinline__ void ldA32(float* sA, const float* __restrict__ A, int lda,
                                      int row0, int k0, int Kc, int tid)
{
    if (k0 + 32 <= Kc) {
#pragma unroll
        for (int it = 0; it < 8; ++it) {
            int lin = it * 256 + tid;          // 0..2047
            int row = lin >> 4, k2 = (lin & 15) * 2;
            float2 v = *reinterpret_cast<const float2*>(A + (size_t)(row0 + row) * lda + k0 + k2);
            v.x = to_tf32(v.x); v.y = to_tf32(v.y);
            *reinterpret_cast<float2*>(sA + row * 40 + k2) = v;
        }
    } else {
#pragma unroll
        for (int it = 0; it < 16; ++it) {
            int lin = it * 256 + tid;
            int row = lin >> 5, kk = lin & 31;
            int gk = k0 + kk;
            sA[row * 40 + kk] = (gk < Kc) ? to_tf32(A[(size_t)(row0 + row) * lda + gk]) : 0.f;
        }
    }
}

// B row-major operand (global B is [Kc, Nc] row-major): Bs[k][n], ld=136
__device__ __forceinline__ void ldB_rm(float* sB, const float* __restrict__ B, int ldb,
                                       int col0, int k0, int Kc, int Nc, int tid)
{
    if (k0 + 32 <= Kc && col0 + 128 <= Nc) {
#pragma unroll
        for (int it = 0; it < 8; ++it) {
            int lin = it * 256 + tid;          // 0..2047
            int k = lin >> 6, n2 = (lin & 63) * 2;
            float2 v = *reinterpret_cast<const float2*>(B + (size_t)(k0 + k) * ldb + col0 + n2);
            v.x = to_tf32(v.x); v.y = to_tf32(v.y);
            *reinterpret_cast<float2*>(sB + k * 136 + n2) = v;
        }
    } else {
#pragma unroll
        for (int it = 0; it < 16; ++it) {
            int lin = it * 256 + tid;
            int k = lin >> 7, n = lin & 127;
            int gk = k0 + k, gn = col0 + n;
            sB[k * 136 + n] = (gk < Kc && gn < Nc) ? to_tf32(B[(size_t)gk * ldb + gn]) : 0.f;
        }
    }
}

// B col-major operand (global B is [Nc, Kc] row-major, used as B^T): Bs[n][k], ld=40
__device__ __forceinline__ void ldB_cm(float* sB, const float* __restrict__ B, int ldb,
                                       int col0, int k0, int Kc, int Nc, int tid)
{
    if (k0 + 32 <= Kc && col0 + 128 <= Nc) {
#pragma unroll
        for (int it = 0; it < 8; ++it) {
            int lin = it * 256 + tid;          // 0..2047
            int n = lin >> 4, k2 = (lin & 15) * 2;
            float2 v = *reinterpret_cast<const float2*>(B + (size_t)(col0 + n) * ldb + k0 + k2);
            v.x = to_tf32(v.x); v.y = to_tf32(v.y);
            *reinterpret_cast<float2*>(sB + n * 40 + k2) = v;
        }
    } else {
#pragma unroll
        for (int it = 0; it < 16; ++it) {
            int lin = it * 256 + tid;
            int n = lin >> 5, kk = lin & 31;
            int gk = k0 + kk, gn = col0 + n;
            sB[n * 40 + kk] = (gk < Kc && gn < Nc) ? to_tf32(B[(size_t)gn * ldb + gk]) : 0.f;
        }
    }
}

// ---------------- WMMA tf32 GEMM: 128x128 block, 8 warps, 32x64 warp tile ----------------
// BT=true : C[2048, Nc] = A[2048, Kc] @ B[Kc, Nc]       (B loaded row-major)
// BT=false: C[2048, Nc] = A[2048, Kc] @ B[Nc, Kc]^T     (B loaded col-major)
template <bool BT>
__global__ void __launch_bounds__(256)
k_wgemm(const float* __restrict__ A, const float* __restrict__ B,
        const float* __restrict__ bias, float* __restrict__ C,
        int Nc, int Kc, int lda, int ldb, int ldc, float scale)
{
    extern __shared__ float sm[];
    const int tid = threadIdx.x;
    const int wid = tid >> 5;
    const int row0 = blockIdx.y * 128;
    const int col0 = blockIdx.x * 128;
    const int wm = (wid >> 1) * 32;   // 4 warps along M
    const int wn = (wid & 1) * 64;    // 2 warps along N

    wmma::fragment<wmma::accumulator, 16, 16, 8, float> acc[2][4];
#pragma unroll
    for (int i = 0; i < 2; ++i)
#pragma unroll
        for (int j = 0; j < 4; ++j)
            wmma::fill_fragment(acc[i][j], 0.f);

    const int NC = (Kc + 31) / 32;

    // prologue: chunk 0 -> buffer 0
    ldA32(sm + AS_OFF(0), A, lda, row0, 0, Kc, tid);
    if (BT) ldB_rm(sm + BS_OFF(0), B, ldb, col0, 0, Kc, Nc, tid);
    else    ldB_cm(sm + BS_OFF(0), B, ldb, col0, 0, Kc, Nc, tid);
    __syncthreads();

    for (int c = 0; c < NC; ++c) {
        const int b = c & 1;
        if (c + 1 < NC) {
            ldA32(sm + AS_OFF(b ^ 1), A, lda, row0, (c + 1) * 32, Kc, tid);
            if (BT) ldB_rm(sm + BS_OFF(b ^ 1), B, ldb, col0, (c + 1) * 32, Kc, Nc, tid);
            else    ldB_cm(sm + BS_OFF(b ^ 1), B, ldb, col0, (c + 1) * 32, Kc, Nc, tid);
        }
        const float* sA = sm + AS_OFF(b);
        const float* sB = sm + BS_OFF(b);
#pragma unroll
        for (int ks = 0; ks < 4; ++ks) {
            wmma::fragment<wmma::matrix_a, 16, 16, 8, wmma::precision::tf32, wmma::row_major> af[2];
            wmma::load_matrix_sync(af[0], sA + (size_t)wm * 40 + ks * 8, 40);
            wmma::load_matrix_sync(af[1], sA + (size_t)(wm + 16) * 40 + ks * 8, 40);
            if (BT) {
#pragma unroll
                for (int j = 0; j < 4; ++j) {
                    wmma::fragment<wmma::matrix_b, 16, 16, 8, wmma::precision::tf32, wmma::row_major> bf;
                    wmma::load_matrix_sync(bf, sB + (size_t)(ks * 8) * 136 + wn + j * 16, 136);
                    wmma::mma_sync(acc[0][j], af[0], bf, acc[0][j]);
                    wmma::mma_sync(acc[1][j], af[1], bf, acc[1][j]);
                }
            } else {
#pragma unroll
                for (int j = 0; j < 4; ++j) {
                    wmma::fragment<wmma::matrix_b, 16, 16, 8, wmma::precision::tf32, wmma::col_major> bf;
                    wmma::load_matrix_sync(bf, sB + (size_t)(wn + j * 16) * 40 + ks * 8, 40);
                    wmma::mma_sync(acc[0][j], af[0], bf, acc[0][j]);
                    wmma::mma_sync(acc[1][j], af[1], bf, acc[1][j]);
                }
            }
        }
        __syncthreads();
    }

    // epilogue: stage accumulators in SMEM (ld=132), then coalesced global store
    float* st = sm;
#pragma unroll
    for (int i = 0; i < 2; ++i)
#pragma unroll
        for (int j = 0; j < 4; ++j)
            wmma::store_matrix_sync(st + (size_t)(wm + i * 16) * 132 + wn + j * 16,
                                    acc[i][j], 132, wmma::mem_row_major);
    __syncthreads();

    const bool hasB = (bias != nullptr);
#pragma unroll
    for (int it = 0; it < 64; ++it) {
        int lin = it * 256 + tid;
        int row = lin >> 7, col = lin & 127;
        int gc = col0 + col;
        if (gc < Nc) {
            float v = st[row * 132 + col] * scale;
            if (hasB) v += bias[gc];
            C[(size_t)(row0 + row) * ldc + gc] = v;
        }
    }
}

// ---------------- softmax row stats ----------------
__global__ void k_rowstat()
{
    const int row = blockIdx.x;
    const float* p = g_sc + (size_t)row * Mv;
    __shared__ float red[256];
    const int t = threadIdx.x;

    float m = -3.4e38f;
    for (int j = t; j < Mv; j += 256) m = fmaxf(m, p[j]);
    red[t] = m; __syncthreads();
    for (int s = 128; s > 0; s >>= 1) {
        if (t < s) red[t] = fmaxf(red[t], red[t + s]);
        __syncthreads();
    }
    m = red[0];
    __syncthreads();

    float sum = 0.f;
    for (int j = t; j < Mv; j += 256) sum += expf(p[j] - m);
    red[t] = sum; __syncthreads();
    for (int s = 128; s > 0; s >>= 1) {
        if (t < s) red[t] += red[t + s];
        __syncthreads();
    }
    if (t == 0) { g_rowmax[row] = m; g_rowinv[row] = 1.f / red[0]; }
}

__global__ void k_colsum_part()
{
    const int j = blockIdx.x * 256 + threadIdx.x;
    const int c = blockIdx.y;
    float acc = 0.f;
    const int i0 = c * (Mv / 16), i1 = i0 + (Mv / 16);
    for (int i = i0; i < i1; ++i)
        acc += expf(g_sc[(size_t)i * Mv + j] - g_rowmax[i]) * g_rowinv[i];
    g_spart[c * Mv + j] = acc;
}

__global__ void k_s_reduce()
{
    const int j = blockIdx.x * 256 + threadIdx.x;
    float acc = 0.f;
    for (int c = 0; c < 16; ++c) acc += g_spart[c * Mv + j];
    g_s[j] = acc * (1.f / (float)Mv);
}

__global__ void k_u_part(const float* __restrict__ X)
{
    const int j = blockIdx.x * 256 + threadIdx.x;
    if (j >= Dv) return;
    const int c = blockIdx.y;
    const int i0 = c * (Mv / 16), i1 = i0 + (Mv / 16);
    float acc = 0.f;
    for (int i = i0; i < i1; ++i)
        acc = fmaf(g_s[i], X[(size_t)i * Dv + j], acc);
    g_upart[c * Dv + j] = acc;
}

__global__ void k_u_reduce()
{
    const int j = blockIdx.x * 256 + threadIdx.x;
    if (j >= Dv) return;
    float acc = 0.f;
    for (int c = 0; c < 16; ++c) acc += g_upart[c * Dv + j];
    g_u[j] = acc;
}

__global__ void k_ctx_part(const float* __restrict__ Wv)
{
    const int j = blockIdx.x * 256 + threadIdx.x;
    if (j >= Dv) return;
    const int c = blockIdx.y;
    const int CR = (Dv + 31) / 32;
    const int i0 = c * CR;
    const int i1 = min(i0 + CR, Dv);
    float acc = 0.f;
    for (int i = i0; i < i1; ++i)
        acc = fmaf(g_u[i], Wv[(size_t)i * Dv + j], acc);
    g_cpart[c * Dv + j] = acc;
}

__global__ void k_ctx_reduce(const float* __restrict__ bv)
{
    const int j = blockIdx.x * 256 + threadIdx.x;
    if (j >= Dv) return;
    float acc = 0.f;
    for (int c = 0; c < 32; ++c) acc += g_cpart[c * Dv + j];
    g_vals[j] = acc + bv[j];
}

__global__ void k_sweep1_part(const float* __restrict__ wmu,
                              const float* __restrict__ wsg,
                              const float* __restrict__ ew)
{
    const int jl = blockIdx.x * 256 + threadIdx.x;
    if (jl >= OUTC) return;
    const int j = Dv + jl;
    const int c = blockIdx.y;
    const int SR = (Dv + 63) / 64;
    const int i0 = c * SR;
    const int i1 = min(i0 + SR, Dv);
    float acc = 0.f;
    for (int i = i0; i < i1; ++i) {
        size_t idx = (size_t)i * Nv + j;
        acc = fmaf(g_vals[i], fmaf(wsg[idx], ew[idx], wmu[idx]), acc);
    }
    g_zpart[c * OUTC + jl] = acc;
}

__global__ void k_sweep1_reduce(const float* __restrict__ bmu,
                                const float* __restrict__ bsg,
                                const float* __restrict__ eb)
{
    const int jl = blockIdx.x * 256 + threadIdx.x;
    if (jl >= OUTC) return;
    const int j = Dv + jl;
    float z = 0.f;
    for (int c = 0; c < 64; ++c) z += g_zpart[c * OUTC + jl];
    float b = fmaf(bsg[j], eb[j], bmu[j]);
    g_vals[j] = tanhf(z + b);
}

__global__ void k_sweep2_part(const float* __restrict__ wmu,
                              const float* __restrict__ wsg,
                              const float* __restrict__ ew)
{
    const int i = blockIdx.x * 256 + threadIdx.x;
    float a[Ov];
#pragma unroll
    for (int o = 0; o < Ov; ++o) a[o] = 0.f;
    if (i < Nv) {
        const float vi = g_vals[i];
        const size_t base = (size_t)i * Nv + (Dv + Hv);
#pragma unroll
        for (int o = 0; o < Ov; ++o)
            a[o] = vi * fmaf(wsg[base + o], ew[base + o], wmu[base + o]);
    }
    __shared__ float red[256];
    const int t = threadIdx.x;
#pragma unroll
    for (int o = 0; o < Ov; ++o) {
        red[t] = a[o];
        __syncthreads();
        for (int s = 128; s > 0; s >>= 1) {
            if (t < s) red[t] += red[t + s];
            __syncthreads();
        }
        if (t == 0) g_opart[blockIdx.x * Ov + o] = red[0];
        __syncthreads();
    }
}

__global__ void k_final(float* __restrict__ out,
                        const float* __restrict__ bmu,
                        const float* __restrict__ bsg,
                        const float* __restrict__ eb)
{
    const int t = threadIdx.x;
    if (t < Ov) {
        float z = 0.f;
        for (int c = 0; c < 33; ++c) z += g_opart[c * Ov + t];
        const int j = Dv + Hv + t;
        float b = fmaf(bsg[j], eb[j], bmu[j]);
        float h = tanhf(z + b);
        out[t] = 1.f / (1.f + expf(-h));
    }
}

// ---------------- launch ----------------
extern "C" void kernel_launch(void* const* d_in, const int* in_sizes, int n_in,
                              void* d_out, int out_size)
{
    const float* X   = (const float*)d_in[0];
    const float* Wq  = (const float*)d_in[1];
    const float* bq  = (const float*)d_in[2];
    const float* Wk  = (const float*)d_in[3];
    const float* bk  = (const float*)d_in[4];
    const float* Wv  = (const float*)d_in[5];
    const float* bv  = (const float*)d_in[6];
    const float* wmu = (const float*)d_in[7];
    const float* wsg = (const float*)d_in[8];
    const float* bmu = (const float*)d_in[9];
    const float* bsg = (const float*)d_in[10];
    const float* ew  = (const float*)d_in[11];
    const float* eb  = (const float*)d_in[12];
    float* out = (float*)d_out;

    float *pq = nullptr, *pk = nullptr, *psc = nullptr;
    cudaGetSymbolAddress((void**)&pq,  g_q);
    cudaGetSymbolAddress((void**)&pk,  g_k);
    cudaGetSymbolAddress((void**)&psc, g_sc);

    cudaFuncSetAttribute(k_wgemm<true>,  cudaFuncAttributeMaxDynamicSharedMemorySize, GEMM_SMEM);
    cudaFuncSetAttribute(k_wgemm<false>, cudaFuncAttributeMaxDynamicSharedMemorySize, GEMM_SMEM);

    const float scScale = (float)(1.0 / sqrt((double)Dv));

    // q = X @ Wq + bq ; k = X @ Wk + bk
    dim3 gBig((Dv + 127) / 128, Mv / 128);       // 61 x 16
    k_wgemm<true><<<gBig, 256, GEMM_SMEM>>>(X, Wq, bq, pq, Dv, Dv, Dv, Dv, Dv, 1.f);
    k_wgemm<true><<<gBig, 256, GEMM_SMEM>>>(X, Wk, bk, pk, Dv, Dv, Dv, Dv, Dv, 1.f);

    // scores = q @ k^T / sqrt(D)
    dim3 gSc(Mv / 128, Mv / 128);                // 16 x 16
    k_wgemm<false><<<gSc, 256, GEMM_SMEM>>>(pq, pk, nullptr, psc, Mv, Dv, Dv, Dv, Mv, scScale);

    k_rowstat<<<Mv, 256>>>();
    k_colsum_part<<<dim3(Mv / 256, 16), 256>>>();
    k_s_reduce<<<Mv / 256, 256>>>();

    k_u_part<<<dim3((Dv + 255) / 256, 16), 256>>>(X);
    k_u_reduce<<<(Dv + 255) / 256, 256>>>();

    k_ctx_part<<<dim3((Dv + 255) / 256, 32), 256>>>(Wv);
    k_ctx_reduce<<<(Dv + 255) / 256, 256>>>(bv);

    k_sweep1_part<<<dim3((OUTC + 255) / 256, 64), 256>>>(wmu, wsg, ew);
    k_sweep1_reduce<<<(OUTC + 255) / 256, 256>>>(bmu, bsg, eb);

    k_sweep2_part<<<(Nv + 255) / 256, 256>>>(wmu, wsg, ew);
    k_final<<<1, 32>>>(out, bmu, bsg, eb);
}

// round 9
// speedup vs baseline: 1.8077x; 1.1927x over previous
#include <cuda_runtime.h>
#include <math.h>
#include <stdint.h>
#include <mma.h>

using namespace nvcuda;

// Problem dims
#define Dv   7686
#define Mv   2048
#define Hv   512
#define Ov   8
#define Nv   8206          // D + H + O
#define OUTC 520           // H + O

// ---------------- scratch (__device__ globals) ----------------
static __device__ float g_xt[(size_t)Mv * Dv];     // tf32-rounded X
static __device__ float g_wt[(size_t)Dv * Dv];     // tf32-rounded Wq / Wk (reused)
static __device__ float g_q [(size_t)Mv * Dv];
static __device__ float g_k [(size_t)Mv * Dv];
static __device__ float g_sc[(size_t)Mv * Mv];
static __device__ float g_rowmax[Mv];
static __device__ float g_rowinv[Mv];
static __device__ float g_spart[16 * Mv];
static __device__ float g_s[Mv];
static __device__ float g_upart[16 * Dv];
static __device__ float g_u[Dv];
static __device__ float g_cpart[32 * Dv];
static __device__ float g_vals[Nv];
static __device__ float g_zpart[64 * OUTC];
static __device__ float g_opart[33 * Ov];

__device__ __forceinline__ float to_tf32(float x) {
    float r;
    asm("cvt.rna.tf32.f32 %0, %1;" : "=f"(r) : "f"(x));
    return r;
}
__device__ __forceinline__ uint32_t smem_u32(const void* p) {
    uint32_t a;
    asm("{ .reg .u64 t; cvta.to.shared.u64 t, %1; cvt.u32.u64 %0, t; }" : "=r"(a) : "l"(p));
    return a;
}
__device__ __forceinline__ void cp8(uint32_t dst, const void* src, int src_bytes) {
    asm volatile("cp.async.ca.shared.global [%0], [%1], 8, %2;"
                 :: "r"(dst), "l"(src), "r"(src_bytes));
}
#define CP_COMMIT() asm volatile("cp.async.commit_group;" ::: "memory")
#define CP_WAIT1()  asm volatile("cp.async.wait_group 1;" ::: "memory")
#define CP_WAIT0()  asm volatile("cp.async.wait_group 0;" ::: "memory")

// ---------------- SMEM layout (floats), 3 stages ----------------
// per stage: A 128x36 (4608) + B (col-major 128x36 = 4608, row-major 32x132 = 4224)
// fixed stage stride 9216 floats; epilogue staging (128x132) reuses the area.
#define STAGE_F    9216
#define GEMM_SMEM  (3 * STAGE_F * 4)   /* 110592 bytes */

// ---------------- cp.async tf32 GEMM: 128x128 block, 8 warps, 32x64 warp tile ------
// Operands must already be tf32-rounded. Row strides are 8-byte aligned (lda even).
// BT=true : C[2048, Nc] = A[2048, Kc] @ B[Kc, Nc]       (B row-major tiles)
// BT=false: C[2048, Nc] = A[2048, Kc] @ B[Nc, Kc]^T     (B col-major tiles)
template <bool BT>
__global__ void __launch_bounds__(256, 2)
k_cgemm(const float* __restrict__ A, const float* __restrict__ B,
        const float* __restrict__ bias, float* __restrict__ C,
        int Nc, int Kc, int lda, int ldb, int ldc, float scale, int roundOut)
{
    extern __shared__ float sm[];
    const uint32_t smb = smem_u32(sm);
    const int tid = threadIdx.x;
    const int wid = tid >> 5;
    const int row0 = blockIdx.y * 128;
    const int col0 = blockIdx.x * 128;
    const int wm = (wid >> 1) * 32;   // 4 warps along M
    const int wn = (wid & 1) * 64;    // 2 warps along N
    const int NC = (Kc + 31) / 32;

    wmma::fragment<wmma::accumulator, 16, 16, 8, float> acc[2][4];
#pragma unroll
    for (int i = 0; i < 2; ++i)
#pragma unroll
        for (int j = 0; j < 4; ++j)
            wmma::fill_fragment(acc[i][j], 0.f);

    auto issue = [&](int c) {
        if (c >= NC) { CP_COMMIT(); return; }
        const int s = c % 3;
        const uint32_t sA = smb + (uint32_t)(s * STAGE_F) * 4u;
        const uint32_t sB = sA + 4608u * 4u;
        const int k0 = c * 32;
        // A tile: 128 rows x 32 k (float2 per thread x 8)
#pragma unroll
        for (int it = 0; it < 8; ++it) {
            int lin = it * 256 + tid;
            int row = lin >> 4, k2 = (lin & 15) * 2;
            int gk = k0 + k2;
            const float* src = (gk < Kc) ? (A + (size_t)(row0 + row) * lda + gk) : A;
            cp8(sA + (uint32_t)(row * 36 + k2) * 4u, src, (gk < Kc) ? 8 : 0);
        }
        if (BT) {
            // B row-major tile: 32 k x 128 n, ld=132
#pragma unroll
            for (int it = 0; it < 8; ++it) {
                int lin = it * 256 + tid;
                int k = lin >> 6, n2 = (lin & 63) * 2;
                int gk = k0 + k, gn = col0 + n2;
                bool ok = (gk < Kc) && (gn < Nc);
                const float* src = ok ? (B + (size_t)gk * ldb + gn) : B;
                cp8(sB + (uint32_t)(k * 132 + n2) * 4u, src, ok ? 8 : 0);
            }
        } else {
            // B col-major tile: 128 n x 32 k, ld=36
#pragma unroll
            for (int it = 0; it < 8; ++it) {
                int lin = it * 256 + tid;
                int n = lin >> 4, k2 = (lin & 15) * 2;
                int gk = k0 + k2, gn = col0 + n;
                bool ok = (gk < Kc) && (gn < Nc);
                const float* src = ok ? (B + (size_t)gn * ldb + gk) : B;
                cp8(sB + (uint32_t)(n * 36 + k2) * 4u, src, ok ? 8 : 0);
            }
        }
        CP_COMMIT();
    };

    issue(0);
    issue(1);

    for (int c = 0; c < NC; ++c) {
        CP_WAIT1();            // stage c complete (stage c+1 may be in flight)
        __syncthreads();       // visible to all warps; prev compute done
        issue(c + 2);          // refill stage (c+2)%3 (consumed at iter c-1)

        const int s = c % 3;
        const float* sA = sm + s * STAGE_F;
        const float* sB = sA + 4608;
#pragma unroll
        for (int ks = 0; ks < 4; ++ks) {
            wmma::fragment<wmma::matrix_a, 16, 16, 8, wmma::precision::tf32, wmma::row_major> af[2];
            wmma::load_matrix_sync(af[0], sA + (size_t)wm * 36 + ks * 8, 36);
            wmma::load_matrix_sync(af[1], sA + (size_t)(wm + 16) * 36 + ks * 8, 36);
            if (BT) {
#pragma unroll
                for (int j = 0; j < 4; ++j) {
                    wmma::fragment<wmma::matrix_b, 16, 16, 8, wmma::precision::tf32, wmma::row_major> bf;
                    wmma::load_matrix_sync(bf, sB + (size_t)(ks * 8) * 132 + wn + j * 16, 132);
                    wmma::mma_sync(acc[0][j], af[0], bf, acc[0][j]);
                    wmma::mma_sync(acc[1][j], af[1], bf, acc[1][j]);
                }
            } else {
#pragma unroll
                for (int j = 0; j < 4; ++j) {
                    wmma::fragment<wmma::matrix_b, 16, 16, 8, wmma::precision::tf32, wmma::col_major> bf;
                    wmma::load_matrix_sync(bf, sB + (size_t)(wn + j * 16) * 36 + ks * 8, 36);
                    wmma::mma_sync(acc[0][j], af[0], bf, acc[0][j]);
                    wmma::mma_sync(acc[1][j], af[1], bf, acc[1][j]);
                }
            }
        }
        __syncthreads();
    }

    CP_WAIT0();
    __syncthreads();

    // epilogue: stage accumulators in SMEM (ld=132), then coalesced global store
    float* st = sm;
#pragma unroll
    for (int i = 0; i < 2; ++i)
#pragma unroll
        for (int j = 0; j < 4; ++j)
            wmma::store_matrix_sync(st + (size_t)(wm + i * 16) * 132 + wn + j * 16,
                                    acc[i][j], 132, wmma::mem_row_major);
    __syncthreads();

    const bool hasB = (bias != nullptr);
#pragma unroll
    for (int it = 0; it < 64; ++it) {
        int lin = it * 256 + tid;
        int row = lin >> 7, col = lin & 127;
        int gc = col0 + col;
        if (gc < Nc) {
            float v = st[row * 132 + col] * scale;
            if (hasB) v += bias[gc];
            if (roundOut) v = to_tf32(v);
            C[(size_t)(row0 + row) * ldc + gc] = v;
        }
    }
}

// ---------------- fp32 -> tf32 rounding pass (float2 vectorized) ----------------
__global__ void k_round(const float* __restrict__ in, float* __restrict__ out, size_t n2)
{
    size_t i = (size_t)blockIdx.x * blockDim.x + threadIdx.x;
    const size_t stride = (size_t)gridDim.x * blockDim.x;
    for (; i < n2; i += stride) {
        float2 v = reinterpret_cast<const float2*>(in)[i];
        v.x = to_tf32(v.x); v.y = to_tf32(v.y);
        reinterpret_cast<float2*>(out)[i] = v;
    }
}

// ---------------- softmax row stats ----------------
__global__ void k_rowstat()
{
    const int row = blockIdx.x;
    const float* p = g_sc + (size_t)row * Mv;
    __shared__ float red[256];
    const int t = threadIdx.x;

    float m = -3.4e38f;
    for (int j = t; j < Mv; j += 256) m = fmaxf(m, p[j]);
    red[t] = m; __syncthreads();
    for (int s = 128; s > 0; s >>= 1) {
        if (t < s) red[t] = fmaxf(red[t], red[t + s]);
        __syncthreads();
    }
    m = red[0];
    __syncthreads();

    float sum = 0.f;
    for (int j = t; j < Mv; j += 256) sum += expf(p[j] - m);
    red[t] = sum; __syncthreads();
    for (int s = 128; s > 0; s >>= 1) {
        if (t < s) red[t] += red[t + s];
        __syncthreads();
    }
    if (t == 0) { g_rowmax[row] = m; g_rowinv[row] = 1.f / red[0]; }
}

__global__ void k_colsum_part()
{
    const int j = blockIdx.x * 256 + threadIdx.x;
    const int c = blockIdx.y;
    float acc = 0.f;
    const int i0 = c * (Mv / 16), i1 = i0 + (Mv / 16);
    for (int i = i0; i < i1; ++i)
        acc += expf(g_sc[(size_t)i * Mv + j] - g_rowmax[i]) * g_rowinv[i];
    g_spart[c * Mv + j] = acc;
}

__global__ void k_s_reduce()
{
    const int j = blockIdx.x * 256 + threadIdx.x;
    float acc = 0.f;
    for (int c = 0; c < 16; ++c) acc += g_spart[c * Mv + j];
    g_s[j] = acc * (1.f / (float)Mv);
}

__global__ void k_u_part(const float* __restrict__ X)
{
    const int j = blockIdx.x * 256 + threadIdx.x;
    if (j >= Dv) return;
    const int c = blockIdx.y;
    const int i0 = c * (Mv / 16), i1 = i0 + (Mv / 16);
    float acc = 0.f;
    for (int i = i0; i < i1; ++i)
        acc = fmaf(g_s[i], X[(size_t)i * Dv + j], acc);
    g_upart[c * Dv + j] = acc;
}

__global__ void k_u_reduce()
{
    const int j = blockIdx.x * 256 + threadIdx.x;
    if (j >= Dv) return;
    float acc = 0.f;
    for (int c = 0; c < 16; ++c) acc += g_upart[c * Dv + j];
    g_u[j] = acc;
}

__global__ void k_ctx_part(const float* __restrict__ Wv)
{
    const int j = blockIdx.x * 256 + threadIdx.x;
    if (j >= Dv) return;
    const int c = blockIdx.y;
    const int CR = (Dv + 31) / 32;
    const int i0 = c * CR;
    const int i1 = min(i0 + CR, Dv);
    float acc = 0.f;
    for (int i = i0; i < i1; ++i)
        acc = fmaf(g_u[i], Wv[(size_t)i * Dv + j], acc);
    g_cpart[c * Dv + j] = acc;
}

__global__ void k_ctx_reduce(const float* __restrict__ bv)
{
    const int j = blockIdx.x * 256 + threadIdx.x;
    if (j >= Dv) return;
    float acc = 0.f;
    for (int c = 0; c < 32; ++c) acc += g_cpart[c * Dv + j];
    g_vals[j] = acc + bv[j];
}

__global__ void k_sweep1_part(const float* __restrict__ wmu,
                              const float* __restrict__ wsg,
                              const float* __restrict__ ew)
{
    const int jl = blockIdx.x * 256 + threadIdx.x;
    if (jl >= OUTC) return;
    const int j = Dv + jl;
    const int c = blockIdx.y;
    const int SR = (Dv + 63) / 64;
    const int i0 = c * SR;
    const int i1 = min(i0 + SR, Dv);
    float acc = 0.f;
    for (int i = i0; i < i1; ++i) {
        size_t idx = (size_t)i * Nv + j;
        acc = fmaf(g_vals[i], fmaf(wsg[idx], ew[idx], wmu[idx]), acc);
    }
    g_zpart[c * OUTC + jl] = acc;
}

__global__ void k_sweep1_reduce(const float* __restrict__ bmu,
                                const float* __restrict__ bsg,
                                const float* __restrict__ eb)
{
    const int jl = blockIdx.x * 256 + threadIdx.x;
    if (jl >= OUTC) return;
    const int j = Dv + jl;
    float z = 0.f;
    for (int c = 0; c < 64; ++c) z += g_zpart[c * OUTC + jl];
    float b = fmaf(bsg[j], eb[j], bmu[j]);
    g_vals[j] = tanhf(z + b);
}

__global__ void k_sweep2_part(const float* __restrict__ wmu,
                              const float* __restrict__ wsg,
                              const float* __restrict__ ew)
{
    const int i = blockIdx.x * 256 + threadIdx.x;
    float a[Ov];
#pragma unroll
    for (int o = 0; o < Ov; ++o) a[o] = 0.f;
    if (i < Nv) {
        const float vi = g_vals[i];
        const size_t base = (size_t)i * Nv + (Dv + Hv);
#pragma unroll
        for (int o = 0; o < Ov; ++o)
            a[o] = vi * fmaf(wsg[base + o], ew[base + o], wmu[base + o]);
    }
    __shared__ float red[256];
    const int t = threadIdx.x;
#pragma unroll
    for (int o = 0; o < Ov; ++o) {
        red[t] = a[o];
        __syncthreads();
        for (int s = 128; s > 0; s >>= 1) {
            if (t < s) red[t] += red[t + s];
            __syncthreads();
        }
        if (t == 0) g_opart[blockIdx.x * Ov + o] = red[0];
        __syncthreads();
    }
}

__global__ void k_final(float* __restrict__ out,
                        const float* __restrict__ bmu,
                        const float* __restrict__ bsg,
                        const float* __restrict__ eb)
{
    const int t = threadIdx.x;
    if (t < Ov) {
        float z = 0.f;
        for (int c = 0; c < 33; ++c) z += g_opart[c * Ov + t];
        const int j = Dv + Hv + t;
        float b = fmaf(bsg[j], eb[j], bmu[j]);
        float h = tanhf(z + b);
        out[t] = 1.f / (1.f + expf(-h));
    }
}

// ---------------- launch ----------------
extern "C" void kernel_launch(void* const* d_in, const int* in_sizes, int n_in,
                              void* d_out, int out_size)
{
    const float* X   = (const float*)d_in[0];
    const float* Wq  = (const float*)d_in[1];
    const float* bq  = (const float*)d_in[2];
    const float* Wk  = (const float*)d_in[3];
    const float* bk  = (const float*)d_in[4];
    const float* Wv  = (const float*)d_in[5];
    const float* bv  = (const float*)d_in[6];
    const float* wmu = (const float*)d_in[7];
    const float* wsg = (const float*)d_in[8];
    const float* bmu = (const float*)d_in[9];
    const float* bsg = (const float*)d_in[10];
    const float* ew  = (const float*)d_in[11];
    const float* eb  = (const float*)d_in[12];
    float* out = (float*)d_out;

    float *pxt = nullptr, *pwt = nullptr, *pq = nullptr, *pk = nullptr, *psc = nullptr;
    cudaGetSymbolAddress((void**)&pxt, g_xt);
    cudaGetSymbolAddress((void**)&pwt, g_wt);
    cudaGetSymbolAddress((void**)&pq,  g_q);
    cudaGetSymbolAddress((void**)&pk,  g_k);
    cudaGetSymbolAddress((void**)&psc, g_sc);

    cudaFuncSetAttribute(k_cgemm<true>,  cudaFuncAttributeMaxDynamicSharedMemorySize, GEMM_SMEM);
    cudaFuncSetAttribute(k_cgemm<false>, cudaFuncAttributeMaxDynamicSharedMemorySize, GEMM_SMEM);

    const float scScale = (float)(1.0 / sqrt((double)Dv));

    // pre-round operands to tf32 (rna) so the GEMM can cp.async without conversion
    k_round<<<2048, 256>>>(X, pxt, ((size_t)Mv * Dv) / 2);

    dim3 gBig((Dv + 127) / 128, Mv / 128);       // 61 x 16
    dim3 gSc(Mv / 128, Mv / 128);                // 16 x 16

    // q = X @ Wq + bq  (round q to tf32 in epilogue for the scores GEMM)
    k_round<<<4096, 256>>>(Wq, pwt, ((size_t)Dv * Dv) / 2);
    k_cgemm<true><<<gBig, 256, GEMM_SMEM>>>(pxt, pwt, bq, pq, Dv, Dv, Dv, Dv, Dv, 1.f, 1);

    // k = X @ Wk + bk  (reuses the Wq scratch buffer)
    k_round<<<4096, 256>>>(Wk, pwt, ((size_t)Dv * Dv) / 2);
    k_cgemm<true><<<gBig, 256, GEMM_SMEM>>>(pxt, pwt, bk, pk, Dv, Dv, Dv, Dv, Dv, 1.f, 1);

    // scores = q @ k^T / sqrt(D)
    k_cgemm<false><<<gSc, 256, GEMM_SMEM>>>(pq, pk, nullptr, psc, Mv, Dv, Dv, Dv, Mv, scScale, 0);

    k_rowstat<<<Mv, 256>>>();
    k_colsum_part<<<dim3(Mv / 256, 16), 256>>>();
    k_s_reduce<<<Mv / 256, 256>>>();

    k_u_part<<<dim3((Dv + 255) / 256, 16), 256>>>(X);
    k_u_reduce<<<(Dv + 255) / 256, 256>>>();

    k_ctx_part<<<dim3((Dv + 255) / 256, 32), 256>>>(Wv);
    k_ctx_reduce<<<(Dv + 255) / 256, 256>>>(bv);

    k_sweep1_part<<<dim3((OUTC + 255) / 256, 64), 256>>>(wmu, wsg, ew);
    k_sweep1_reduce<<<(OUTC + 255) / 256, 256>>>(bmu, bsg, eb);

    k_sweep2_part<<<(Nv + 255) / 256, 256>>>(wmu, wsg, ew);
    k_final<<<1, 32>>>(out, bmu, bsg, eb);
}

// round 11
// speedup vs baseline: 1.9358x; 1.0709x over previous
#include <cuda_runtime.h>
#include <math.h>
#include <stdint.h>
#include <mma.h>

using namespace nvcuda;

// Problem dims
#define Dv   7686
#define Mv   2048
#define Hv   512
#define Ov   8
#define Nv   8206          // D + H + O
#define OUTC 520           // H + O

#define KPAD 7712          // Dv padded to multiple of 32 (241 chunks), 16B-aligned ld
#define LDW  7688          // Dv padded to multiple of 4 (W column stride)

// ---------------- scratch (__device__ globals) ----------------
static __device__ float g_xt[(size_t)Mv * KPAD];              // tf32 X, ld=KPAD, pad cols 0
static __device__ float g_wt[(size_t)KPAD * LDW + 256];       // tf32 Wq/Wk, ld=LDW, pad rows 0 (+slack)
static __device__ float g_q [(size_t)Mv * KPAD];              // q, ld=KPAD, pad cols 0
static __device__ float g_k [(size_t)Mv * KPAD];              // k, ld=KPAD, pad cols 0
static __device__ float g_sc[(size_t)Mv * Mv];
static __device__ float g_rowmax[Mv];
static __device__ float g_rowinv[Mv];
static __device__ float g_spart[16 * Mv];
static __device__ float g_s[Mv];
static __device__ float g_upart[16 * Dv];
static __device__ float g_u[Dv];
static __device__ float g_cpart[32 * Dv];
static __device__ float g_vals[Nv];
static __device__ float g_zpart[64 * OUTC];
static __device__ float g_opart[33 * Ov];

__device__ __forceinline__ float to_tf32(float x) {
    float r;
    asm("cvt.rna.tf32.f32 %0, %1;" : "=f"(r) : "f"(x));
    return r;
}
__device__ __forceinline__ uint32_t smem_u32(const void* p) {
    uint32_t a;
    asm("{ .reg .u64 t; cvta.to.shared.u64 t, %1; cvt.u32.u64 %0, t; }" : "=r"(a) : "l"(p));
    return a;
}
__device__ __forceinline__ void cp16(uint32_t dst, const void* src) {
    asm volatile("cp.async.cg.shared.global [%0], [%1], 16;" :: "r"(dst), "l"(src));
}
#define CP_COMMIT() asm volatile("cp.async.commit_group;" ::: "memory")
#define CP_WAIT2()  asm volatile("cp.async.wait_group 2;" ::: "memory")
#define CP_WAIT0()  asm volatile("cp.async.wait_group 0;" ::: "memory")

// ---------------- SMEM layout (floats), 3 stages ----------------
// per stage: A 128x36 (4608 floats) + B (col-major 128x36=4608 or row-major 32x132=4224)
#define STAGE_F    9216
#define GEMM_SMEM  (3 * STAGE_F * 4)   /* 110592 bytes */

// ---------------- cp.async tf32 GEMM: 128x128 block, 8 warps, 32x64 warp tile ------
// Operands pre-rounded to tf32 and padded: no bounds checks in the mainloop.
// BT=true : C = A[.,Kc] @ B[Kc, ...]   (B row-major tiles, ldb=LDW)
// BT=false: C = A @ B^T                (B col-major tiles, ldb=lda)
template <bool BT>
__global__ void __launch_bounds__(256, 2)
k_cgemm(const float* __restrict__ A, const float* __restrict__ B,
        const float* __restrict__ bias, float* __restrict__ C,
        int Nc, int NcPad, int Kc, int lda, int ldb, int ldc, float scale, int roundOut)
{
    extern __shared__ float sm[];
    const uint32_t smb = smem_u32(sm);
    const int tid = threadIdx.x;
    const int wid = tid >> 5;
    const int row0 = blockIdx.y * 128;
    const int col0 = blockIdx.x * 128;
    const int wm = (wid >> 1) * 32;   // 4 warps along M
    const int wn = (wid & 1) * 64;    // 2 warps along N
    const int NC = Kc / 32;           // Kc is a multiple of 32

    wmma::fragment<wmma::accumulator, 16, 16, 8, float> acc[2][4];
#pragma unroll
    for (int i = 0; i < 2; ++i)
#pragma unroll
        for (int j = 0; j < 4; ++j)
            wmma::fill_fragment(acc[i][j], 0.f);

    auto issue = [&](int c) {
        if (c >= NC) { CP_COMMIT(); return; }
        const int s = c % 3;
        const uint32_t sA = smb + (uint32_t)(s * STAGE_F) * 4u;
        const uint32_t sB = sA + 4608u * 4u;
        const int k0 = c * 32;
        // A tile: 128 rows x 32 k, 16B per op, 4 ops/thread
#pragma unroll
        for (int it = 0; it < 4; ++it) {
            int lin = it * 256 + tid;
            int row = lin >> 3, k4 = (lin & 7) * 4;
            cp16(sA + (uint32_t)(row * 36 + k4) * 4u,
                 A + (size_t)(row0 + row) * lda + k0 + k4);
        }
        if (BT) {
            // B row-major tile: 32 k x 128 n, ld=132
#pragma unroll
            for (int it = 0; it < 4; ++it) {
                int lin = it * 256 + tid;
                int k = lin >> 5, n4 = (lin & 31) * 4;
                cp16(sB + (uint32_t)(k * 132 + n4) * 4u,
                     B + (size_t)(k0 + k) * ldb + col0 + n4);
            }
        } else {
            // B col-major tile: 128 n x 32 k, ld=36
#pragma unroll
            for (int it = 0; it < 4; ++it) {
                int lin = it * 256 + tid;
                int n = lin >> 3, k4 = (lin & 7) * 4;
                cp16(sB + (uint32_t)(n * 36 + k4) * 4u,
                     B + (size_t)(col0 + n) * ldb + k0 + k4);
            }
        }
        CP_COMMIT();
    };

    issue(0);
    issue(1);

    for (int c = 0; c < NC; ++c) {
        issue(c + 2);          // refill stage (c+2)%3 (consumed at iter c-1, barrier passed)
        CP_WAIT2();            // stage c complete (c+1, c+2 may be in flight)
        __syncthreads();

        const int s = c % 3;
        const float* sA = sm + s * STAGE_F;
        const float* sB = sA + 4608;
#pragma unroll
        for (int ks = 0; ks < 4; ++ks) {
            wmma::fragment<wmma::matrix_a, 16, 16, 8, wmma::precision::tf32, wmma::row_major> af[2];
            wmma::load_matrix_sync(af[0], sA + (size_t)wm * 36 + ks * 8, 36);
            wmma::load_matrix_sync(af[1], sA + (size_t)(wm + 16) * 36 + ks * 8, 36);
            if (BT) {
#pragma unroll
                for (int j = 0; j < 4; ++j) {
                    wmma::fragment<wmma::matrix_b, 16, 16, 8, wmma::precision::tf32, wmma::row_major> bf;
                    wmma::load_matrix_sync(bf, sB + (size_t)(ks * 8) * 132 + wn + j * 16, 132);
                    wmma::mma_sync(acc[0][j], af[0], bf, acc[0][j]);
                    wmma::mma_sync(acc[1][j], af[1], bf, acc[1][j]);
                }
            } else {
#pragma unroll
                for (int j = 0; j < 4; ++j) {
                    wmma::fragment<wmma::matrix_b, 16, 16, 8, wmma::precision::tf32, wmma::col_major> bf;
                    wmma::load_matrix_sync(bf, sB + (size_t)(wn + j * 16) * 36 + ks * 8, 36);
                    wmma::mma_sync(acc[0][j], af[0], bf, acc[0][j]);
                    wmma::mma_sync(acc[1][j], af[1], bf, acc[1][j]);
                }
            }
        }
        __syncthreads();
    }

    CP_WAIT0();
    __syncthreads();

    // epilogue: stage accumulators in SMEM (ld=132), then coalesced global store
    float* st = sm;
#pragma unroll
    for (int i = 0; i < 2; ++i)
#pragma unroll
        for (int j = 0; j < 4; ++j)
            wmma::store_matrix_sync(st + (size_t)(wm + i * 16) * 132 + wn + j * 16,
                                    acc[i][j], 132, wmma::mem_row_major);
    __syncthreads();

    const bool hasB = (bias != nullptr);
#pragma unroll
    for (int it = 0; it < 64; ++it) {
        int lin = it * 256 + tid;
        int row = lin >> 7, col = lin & 127;
        int gc = col0 + col;
        if (gc < NcPad) {
            float v = 0.f;
            if (gc < Nc) {
                v = st[row * 132 + col] * scale;
                if (hasB) v += bias[gc];
                if (roundOut) v = to_tf32(v);
            }
            C[(size_t)(row0 + row) * ldc + gc] = v;   // pad cols get exact 0
        }
    }
}

// ---------------- fp32 -> tf32 round + pad pass ----------------
// out[r*ldo + j] = tf32(in[r*cols + j]) for j < cols, else 0.
__global__ void k_round_pad(const float* __restrict__ in, float* __restrict__ out,
                            int cols, int ldo)
{
    const int r = blockIdx.y;
    const int j = blockIdx.x * 256 + threadIdx.x;
    if (j < ldo)
        out[(size_t)r * ldo + j] = (j < cols) ? to_tf32(in[(size_t)r * cols + j]) : 0.f;
}

__global__ void k_zero(float* __restrict__ p, size_t n)
{
    size_t i = (size_t)blockIdx.x * blockDim.x + threadIdx.x;
    const size_t stride = (size_t)gridDim.x * blockDim.x;
    for (; i < n; i += stride) p[i] = 0.f;
}

// ---------------- softmax row stats ----------------
__global__ void k_rowstat()
{
    const int row = blockIdx.x;
    const float* p = g_sc + (size_t)row * Mv;
    __shared__ float red[256];
    const int t = threadIdx.x;

    float m = -3.4e38f;
    for (int j = t; j < Mv; j += 256) m = fmaxf(m, p[j]);
    red[t] = m; __syncthreads();
    for (int s = 128; s > 0; s >>= 1) {
        if (t < s) red[t] = fmaxf(red[t], red[t + s]);
        __syncthreads();
    }
    m = red[0];
    __syncthreads();

    float sum = 0.f;
    for (int j = t; j < Mv; j += 256) sum += expf(p[j] - m);
    red[t] = sum; __syncthreads();
    for (int s = 128; s > 0; s >>= 1) {
        if (t < s) red[t] += red[t + s];
        __syncthreads();
    }
    if (t == 0) { g_rowmax[row] = m; g_rowinv[row] = 1.f / red[0]; }
}

__global__ void k_colsum_part()
{
    const int j = blockIdx.x * 256 + threadIdx.x;
    const int c = blockIdx.y;
    float acc = 0.f;
    const int i0 = c * (Mv / 16), i1 = i0 + (Mv / 16);
    for (int i = i0; i < i1; ++i)
        acc += expf(g_sc[(size_t)i * Mv + j] - g_rowmax[i]) * g_rowinv[i];
    g_spart[c * Mv + j] = acc;
}

__global__ void k_s_reduce()
{
    const int j = blockIdx.x * 256 + threadIdx.x;
    float acc = 0.f;
    for (int c = 0; c < 16; ++c) acc += g_spart[c * Mv + j];
    g_s[j] = acc * (1.f / (float)Mv);
}

__global__ void k_u_part(const float* __restrict__ X)
{
    const int j = blockIdx.x * 256 + threadIdx.x;
    if (j >= Dv) return;
    const int c = blockIdx.y;
    const int i0 = c * (Mv / 16), i1 = i0 + (Mv / 16);
    float acc = 0.f;
    for (int i = i0; i < i1; ++i)
        acc = fmaf(g_s[i], X[(size_t)i * Dv + j], acc);
    g_upart[c * Dv + j] = acc;
}

__global__ void k_u_reduce()
{
    const int j = blockIdx.x * 256 + threadIdx.x;
    if (j >= Dv) return;
    float acc = 0.f;
    for (int c = 0; c < 16; ++c) acc += g_upart[c * Dv + j];
    g_u[j] = acc;
}

__global__ void k_ctx_part(const float* __restrict__ Wv)
{
    const int j = blockIdx.x * 256 + threadIdx.x;
    if (j >= Dv) return;
    const int c = blockIdx.y;
    const int CR = (Dv + 31) / 32;
    const int i0 = c * CR;
    const int i1 = min(i0 + CR, Dv);
    float acc = 0.f;
    for (int i = i0; i < i1; ++i)
        acc = fmaf(g_u[i], Wv[(size_t)i * Dv + j], acc);
    g_cpart[c * Dv + j] = acc;
}

__global__ void k_ctx_reduce(const float* __restrict__ bv)
{
    const int j = blockIdx.x * 256 + threadIdx.x;
    if (j >= Dv) return;
    float acc = 0.f;
    for (int c = 0; c < 32; ++c) acc += g_cpart[c * Dv + j];
    g_vals[j] = acc + bv[j];
}

__global__ void k_sweep1_part(const float* __restrict__ wmu,
                              const float* __restrict__ wsg,
                              const float* __restrict__ ew)
{
    const int jl = blockIdx.x * 256 + threadIdx.x;
    if (jl >= OUTC) return;
    const int j = Dv + jl;
    const int c = blockIdx.y;
    const int SR = (Dv + 63) / 64;
    const int i0 = c * SR;
    const int i1 = min(i0 + SR, Dv);
    float acc = 0.f;
    for (int i = i0; i < i1; ++i) {
        size_t idx = (size_t)i * Nv + j;
        acc = fmaf(g_vals[i], fmaf(wsg[idx], ew[idx], wmu[idx]), acc);
    }
    g_zpart[c * OUTC + jl] = acc;
}

__global__ void k_sweep1_reduce(const float* __restrict__ bmu,
                                const float* __restrict__ bsg,
                                const float* __restrict__ eb)
{
    const int jl = blockIdx.x * 256 + threadIdx.x;
    if (jl >= OUTC) return;
    const int j = Dv + jl;
    float z = 0.f;
    for (int c = 0; c < 64; ++c) z += g_zpart[c * OUTC + jl];
    float b = fmaf(bsg[j], eb[j], bmu[j]);
    g_vals[j] = tanhf(z + b);
}

__global__ void k_sweep2_part(const float* __restrict__ wmu,
                              const float* __restrict__ wsg,
                              const float* __restrict__ ew)
{
    const int i = blockIdx.x * 256 + threadIdx.x;
    float a[Ov];
#pragma unroll
    for (int o = 0; o < Ov; ++o) a[o] = 0.f;
    if (i < Nv) {
        const float vi = g_vals[i];
        const size_t base = (size_t)i * Nv + (Dv + Hv);
#pragma unroll
        for (int o = 0; o < Ov; ++o)
            a[o] = vi * fmaf(wsg[base + o], ew[base + o], wmu[base + o]);
    }
    __shared__ float red[256];
    const int t = threadIdx.x;
#pragma unroll
    for (int o = 0; o < Ov; ++o) {
        red[t] = a[o];
        __syncthreads();
        for (int s = 128; s > 0; s >>= 1) {
            if (t < s) red[t] += red[t + s];
            __syncthreads();
        }
        if (t == 0) g_opart[blockIdx.x * Ov + o] = red[0];
        __syncthreads();
    }
}

__global__ void k_final(float* __restrict__ out,
                        const float* __restrict__ bmu,
                        const float* __restrict__ bsg,
                        const float* __restrict__ eb)
{
    const int t = threadIdx.x;
    if (t < Ov) {
        float z = 0.f;
        for (int c = 0; c < 33; ++c) z += g_opart[c * Ov + t];
        const int j = Dv + Hv + t;
        float b = fmaf(bsg[j], eb[j], bmu[j]);
        float h = tanhf(z + b);
        out[t] = 1.f / (1.f + expf(-h));
    }
}

// ---------------- launch ----------------
extern "C" void kernel_launch(void* const* d_in, const int* in_sizes, int n_in,
                              void* d_out, int out_size)
{
    const float* X   = (const float*)d_in[0];
    const float* Wq  = (const float*)d_in[1];
    const float* bq  = (const float*)d_in[2];
    const float* Wk  = (const float*)d_in[3];
    const float* bk  = (const float*)d_in[4];
    const float* Wv  = (const float*)d_in[5];
    const float* bv  = (const float*)d_in[6];
    const float* wmu = (const float*)d_in[7];
    const float* wsg = (const float*)d_in[8];
    const float* bmu = (const float*)d_in[9];
    const float* bsg = (const float*)d_in[10];
    const float* ew  = (const float*)d_in[11];
    const float* eb  = (const float*)d_in[12];
    float* out = (float*)d_out;

    float *pxt = nullptr, *pwt = nullptr, *pq = nullptr, *pk = nullptr, *psc = nullptr;
    cudaGetSymbolAddress((void**)&pxt, g_xt);
    cudaGetSymbolAddress((void**)&pwt, g_wt);
    cudaGetSymbolAddress((void**)&pq,  g_q);
    cudaGetSymbolAddress((void**)&pk,  g_k);
    cudaGetSymbolAddress((void**)&psc, g_sc);

    cudaFuncSetAttribute(k_cgemm<true>,  cudaFuncAttributeMaxDynamicSharedMemorySize, GEMM_SMEM);
    cudaFuncSetAttribute(k_cgemm<false>, cudaFuncAttributeMaxDynamicSharedMemorySize, GEMM_SMEM);

    const float scScale = (float)(1.0 / sqrt((double)Dv));

    // tf32-round + pad X into [Mv, KPAD]
    k_round_pad<<<dim3((KPAD + 255) / 256, Mv), 256>>>(X, pxt, Dv, KPAD);
    // zero the pad rows of the W scratch once (rows Dv..KPAD-1)
    k_zero<<<256, 256>>>(pwt + (size_t)Dv * LDW, (size_t)(KPAD - Dv) * LDW + 256);

    dim3 gBig((Dv + 127) / 128, Mv / 128);       // 61 x 16
    dim3 gSc(Mv / 128, Mv / 128);                // 16 x 16

    // q = X @ Wq + bq (tf32-rounded output, pad cols zeroed)
    k_round_pad<<<dim3((LDW + 255) / 256, Dv), 256>>>(Wq, pwt, Dv, LDW);
    k_cgemm<true><<<gBig, 256, GEMM_SMEM>>>(pxt, pwt, bq, pq,
                                            Dv, KPAD, KPAD, KPAD, LDW, KPAD, 1.f, 1);

    // k = X @ Wk + bk (reuses W scratch; pad rows still zero)
    k_round_pad<<<dim3((LDW + 255) / 256, Dv), 256>>>(Wk, pwt, Dv, LDW);
    k_cgemm<true><<<gBig, 256, GEMM_SMEM>>>(pxt, pwt, bk, pk,
                                            Dv, KPAD, KPAD, KPAD, LDW, KPAD, 1.f, 1);

    // scores = q @ k^T / sqrt(D)
    k_cgemm<false><<<gSc, 256, GEMM_SMEM>>>(pq, pk, nullptr, psc,
                                            Mv, Mv, KPAD, KPAD, KPAD, Mv, scScale, 0);

    k_rowstat<<<Mv, 256>>>();
    k_colsum_part<<<dim3(Mv / 256, 16), 256>>>();
    k_s_reduce<<<Mv / 256, 256>>>();

    k_u_part<<<dim3((Dv + 255) / 256, 16), 256>>>(X);
    k_u_reduce<<<(Dv + 255) / 256, 256>>>();

    k_ctx_part<<<dim3((Dv + 255) / 256, 32), 256>>>(Wv);
    k_ctx_reduce<<<(Dv + 255) / 256, 256>>>(bv);

    k_sweep1_part<<<dim3((OUTC + 255) / 256, 64), 256>>>(wmu, wsg, ew);
    k_sweep1_reduce<<<(OUTC + 255) / 256, 256>>>(bmu, bsg, eb);

    k_sweep2_part<<<(Nv + 255) / 256, 256>>>(wmu, wsg, ew);
    k_final<<<1, 32>>>(out, bmu, bsg, eb);
}